// round 2
// baseline (speedup 1.0000x reference)
#include <cuda_runtime.h>

// Problem constants
#define NG   64    // groups
#define ND   16    // per-group input dim
#define NH   8     // hidden per group
#define NB   64    // batch
#define NT   512   // timesteps

// ---------- packed f32x2 helpers (FFMA2: 2 MACs per instruction) ----------
__device__ __forceinline__ unsigned long long pack2f(float lo, float hi) {
    unsigned long long r;
    asm("mov.b64 %0, {%1,%2};" : "=l"(r) : "f"(lo), "f"(hi));
    return r;
}
__device__ __forceinline__ unsigned long long fma2(unsigned long long a,
                                                   unsigned long long b,
                                                   unsigned long long c) {
    unsigned long long d;
    asm("fma.rn.f32x2 %0, %1, %2, %3;" : "=l"(d) : "l"(a), "l"(b), "l"(c));
    return d;
}
__device__ __forceinline__ float hsum2(unsigned long long v) {
    float lo, hi;
    asm("mov.b64 {%0,%1}, %2;" : "=f"(lo), "=f"(hi) : "l"(v));
    return lo + hi;
}

// ---------- fast activations (MUFU-based, ~1e-7 rel err) ----------
__device__ __forceinline__ float fast_sigmoid(float v) {
    return __fdividef(1.0f, 1.0f + __expf(-v));
}
__device__ __forceinline__ float fast_tanh(float v) {
    // tanh(v) = 2*sigmoid(2v) - 1
    return fmaf(2.0f, __fdividef(1.0f, 1.0f + __expf(-2.0f * v)), -1.0f);
}

// One warp per block, 4 (b,g) chains per warp, 8 lanes per chain (lane = hidden unit).
__global__ void __launch_bounds__(32) mcgru_kernel(
    const float* __restrict__ x,      // [B, T, G*D]
    const float* __restrict__ W_ih,   // [G, 3H, D]
    const float* __restrict__ W_hh,   // [G, 3H, H]
    const float* __restrict__ b_ih,   // [G, 3H]
    const float* __restrict__ b_hh,   // [G, 3H]
    float* __restrict__ out)          // [B, T, G, H]
{
    const int lane = threadIdx.x;       // 0..31
    const int sub  = lane >> 3;         // chain within warp: 0..3
    const int l    = lane & 7;          // hidden unit index: 0..7
    const int p    = blockIdx.x * 4 + sub;   // global chain id, < 4096
    const int b    = p >> 6;
    const int g    = p & 63;

    // ---- load per-lane weight rows (gate order: r=rows 0..7, z=8..15, n=16..23) ----
    unsigned long long wih2[3][8];  // W_ih rows (l, l+8, l+16), packed as f32x2 pairs
    float whh[3][8];
#pragma unroll
    for (int r = 0; r < 3; r++) {
        const float* wr = W_ih + ((size_t)g * 24 + r * 8 + l) * ND;
#pragma unroll
        for (int q = 0; q < 8; q++) wih2[r][q] = pack2f(wr[2 * q], wr[2 * q + 1]);
        const float* wh = W_hh + ((size_t)g * 24 + r * 8 + l) * NH;
#pragma unroll
        for (int j = 0; j < 8; j++) whh[r][j] = wh[j];
    }
    // biases: r/z gates can merge b_ih+b_hh; n gate must keep them separate
    const float br  = b_ih[g * 24 + l]      + b_hh[g * 24 + l];
    const float bz  = b_ih[g * 24 + 8 + l]  + b_hh[g * 24 + 8 + l];
    const float bxn = b_ih[g * 24 + 16 + l];
    const float bhn = b_hh[g * 24 + 16 + l];

    // x row for this chain: 16 floats = 4 * 16B; stride per t = 1024 floats = 256 ulonglong2
    const ulonglong2* xp = reinterpret_cast<const ulonglong2*>(
        x + (size_t)b * NT * (NG * ND) + g * ND);
    float* op = out + ((size_t)b * NT * NG + g) * NH + l;   // stride per t: G*H = 512 floats

    float h = 0.0f;

    // software-pipelined x prefetch (gx has no dependency on h)
    ulonglong2 xc[4], xn[4];
#pragma unroll
    for (int q = 0; q < 4; q++) xc[q] = xp[q];

#pragma unroll 2
    for (int t = 0; t < NT; t++) {
        // prefetch next timestep's x (clamped at the end: branch-free, reads last row twice)
        const int tn = (t + 1 < NT) ? (t + 1) : (NT - 1);
        const ulonglong2* xnx = xp + (size_t)tn * 256;
#pragma unroll
        for (int q = 0; q < 4; q++) xn[q] = xnx[q];

        // ---- gx = W_ih_row . x + bias  (packed f32x2: 24 FFMA2 instead of 48 FFMA) ----
        unsigned long long ar = pack2f(br, 0.0f);
        unsigned long long az = pack2f(bz, 0.0f);
        unsigned long long an = pack2f(bxn, 0.0f);
#pragma unroll
        for (int q = 0; q < 4; q++) {
            ar = fma2(wih2[0][2 * q],     xc[q].x, ar);
            ar = fma2(wih2[0][2 * q + 1], xc[q].y, ar);
            az = fma2(wih2[1][2 * q],     xc[q].x, az);
            az = fma2(wih2[1][2 * q + 1], xc[q].y, az);
            an = fma2(wih2[2][2 * q],     xc[q].x, an);
            an = fma2(wih2[2][2 * q + 1], xc[q].y, an);
        }
        const float gxr = hsum2(ar);
        const float gxz = hsum2(az);
        const float gxn = hsum2(an);

        // ---- gh = W_hh_row . h  (h broadcast via 8-wide shuffles) ----
        float ghr = 0.0f, ghz = 0.0f, ghn = bhn;
#pragma unroll
        for (int j = 0; j < 8; j++) {
            const float hj = __shfl_sync(0xffffffffu, h, j, 8);
            ghr = fmaf(whh[0][j], hj, ghr);
            ghz = fmaf(whh[1][j], hj, ghz);
            ghn = fmaf(whh[2][j], hj, ghn);
        }

        // ---- gates (PyTorch order r, z, n) ----
        const float r = fast_sigmoid(gxr + ghr);
        const float z = fast_sigmoid(gxz + ghz);
        const float n = fast_tanh(fmaf(r, ghn, gxn));
        h = fmaf(z, h - n, n);   // (1-z)*n + z*h

        op[(size_t)t * (NG * NH)] = h;

#pragma unroll
        for (int q = 0; q < 4; q++) xc[q] = xn[q];
    }
}

extern "C" void kernel_launch(void* const* d_in, const int* in_sizes, int n_in,
                              void* d_out, int out_size) {
    const float* x    = (const float*)d_in[0];
    const float* W_ih = (const float*)d_in[1];
    const float* W_hh = (const float*)d_in[2];
    const float* b_ih = (const float*)d_in[3];
    const float* b_hh = (const float*)d_in[4];
    float* out = (float*)d_out;

    // 4096 chains / 4 per warp-block = 1024 blocks of 32 threads (good wave balance: ~6.9/SM)
    mcgru_kernel<<<1024, 32>>>(x, W_ih, W_hh, b_ih, b_hh, out);
}

// round 5
// speedup vs baseline: 1.3011x; 1.3011x over previous
#include <cuda_runtime.h>

// Problem constants
#define NG   64    // groups
#define ND   16    // per-group input dim
#define NH   8     // hidden per group
#define NB   64    // batch
#define NT   512   // timesteps

// T-split: 2 segments, balanced at 288 iterations each.
// seg0: t in [0,288) all stored.  seg1: burn-in [224,288), store [288,512).
#define SEG0_STORE 288
#define BURN       64

// ---------- packed f32x2 helpers (FFMA2: 2 MACs per instruction) ----------
__device__ __forceinline__ unsigned long long pack2f(float lo, float hi) {
    unsigned long long r;
    asm("mov.b64 %0, {%1,%2};" : "=l"(r) : "f"(lo), "f"(hi));
    return r;
}
__device__ __forceinline__ unsigned long long fma2(unsigned long long a,
                                                   unsigned long long b,
                                                   unsigned long long c) {
    unsigned long long d;
    asm("fma.rn.f32x2 %0, %1, %2, %3;" : "=l"(d) : "l"(a), "l"(b), "l"(c));
    return d;
}
__device__ __forceinline__ float hsum2(unsigned long long v) {
    float lo, hi;
    asm("mov.b64 {%0,%1}, %2;" : "=f"(lo), "=f"(hi) : "l"(v));
    return lo + hi;
}

// ---------- MUFU.TANH activations (1 MUFU vs ~45cyc exp-based) ----------
__device__ __forceinline__ float mufu_tanh(float v) {
    float r;
    asm("tanh.approx.f32 %0, %1;" : "=f"(r) : "f"(v));
    return r;
}
__device__ __forceinline__ float fast_sigmoid(float v) {
    return fmaf(0.5f, mufu_tanh(0.5f * v), 0.5f);
}

// One GRU step from x-buffer XB (4 x ulonglong2 = 16 floats), updates h.
#define GRU_STEP(XB)                                                          \
    do {                                                                      \
        unsigned long long ar = pack2f(br, 0.0f);                             \
        unsigned long long az = pack2f(bz, 0.0f);                             \
        unsigned long long an = pack2f(bxn, 0.0f);                            \
        _Pragma("unroll")                                                     \
        for (int q = 0; q < 4; q++) {                                         \
            ar = fma2(wih2[0][2 * q],     XB[q].x, ar);                       \
            ar = fma2(wih2[0][2 * q + 1], XB[q].y, ar);                       \
            az = fma2(wih2[1][2 * q],     XB[q].x, az);                       \
            az = fma2(wih2[1][2 * q + 1], XB[q].y, az);                       \
            an = fma2(wih2[2][2 * q],     XB[q].x, an);                       \
            an = fma2(wih2[2][2 * q + 1], XB[q].y, an);                       \
        }                                                                     \
        const float gxr = hsum2(ar);                                          \
        const float gxz = hsum2(az);                                          \
        const float gxn = hsum2(an);                                          \
        float ghr = 0.0f, ghz = 0.0f, ghn = bhn;                              \
        _Pragma("unroll")                                                     \
        for (int j = 0; j < 8; j++) {                                         \
            const float hj = __shfl_sync(0xffffffffu, h, j, 8);               \
            ghr = fmaf(whh[0][j], hj, ghr);                                   \
            ghz = fmaf(whh[1][j], hj, ghz);                                   \
            ghn = fmaf(whh[2][j], hj, ghn);                                   \
        }                                                                     \
        const float rr = fast_sigmoid(gxr + ghr);                             \
        const float zz = fast_sigmoid(gxz + ghz);                             \
        const float nn = mufu_tanh(fmaf(rr, ghn, gxn));                       \
        h = fmaf(zz, h - nn, nn);                                             \
    } while (0)

// 128 threads/block, 4 warps; each warp handles 4 (b,g) chains of one segment.
// 2048 warps total -> 512 blocks. Cap regs at 128 => 4 blocks (16 warps)/SM.
__global__ void __launch_bounds__(128, 4) mcgru_kernel(
    const float* __restrict__ x,      // [B, T, G*D]
    const float* __restrict__ W_ih,   // [G, 3H, D]
    const float* __restrict__ W_hh,   // [G, 3H, H]
    const float* __restrict__ b_ih,   // [G, 3H]
    const float* __restrict__ b_hh,   // [G, 3H]
    float* __restrict__ out)          // [B, T, G, H]
{
    const int warp = (blockIdx.x * 128 + threadIdx.x) >> 5;   // 0..2047
    const int lane = threadIdx.x & 31;
    const int sub  = lane >> 3;         // chain within warp: 0..3
    const int l    = lane & 7;          // hidden unit: 0..7
    const int seg  = warp >> 10;        // 0 or 1
    const int p    = ((warp & 1023) << 2) | sub;  // chain id 0..4095
    const int b    = p >> 6;
    const int g    = p & 63;

    // ---- per-lane weight rows (gate order: r rows 0..7, z 8..15, n 16..23) ----
    unsigned long long wih2[3][8];
    float whh[3][8];
#pragma unroll
    for (int r = 0; r < 3; r++) {
        const float* wr = W_ih + ((size_t)g * 24 + r * 8 + l) * ND;
#pragma unroll
        for (int q = 0; q < 8; q++) wih2[r][q] = pack2f(wr[2 * q], wr[2 * q + 1]);
        const float* wh = W_hh + ((size_t)g * 24 + r * 8 + l) * NH;
#pragma unroll
        for (int j = 0; j < 8; j++) whh[r][j] = wh[j];
    }
    const float br  = b_ih[g * 24 + l]      + b_hh[g * 24 + l];
    const float bz  = b_ih[g * 24 + 8 + l]  + b_hh[g * 24 + 8 + l];
    const float bxn = b_ih[g * 24 + 16 + l];
    const float bhn = b_hh[g * 24 + 16 + l];

    // segment bounds
    const int t0     = seg ? (SEG0_STORE - BURN) : 0;   // 224 or 0
    const int nburn  = seg ? BURN : 0;                  // 64 or 0
    const int nstore = seg ? (NT - SEG0_STORE) : SEG0_STORE;  // 224 or 288

    // x row: 16 floats = 4 ulonglong2; per-t stride = 1024 floats = 256 ulonglong2
    const ulonglong2* xp = reinterpret_cast<const ulonglong2*>(
        x + (size_t)b * NT * (NG * ND) + g * ND);
    // out index [b][t][g][h]; base at first stored t
    float* op = out + ((size_t)b * NT * NG + g) * NH + l
                    + (size_t)(t0 + nburn) * (NG * NH);

    float h = 0.0f;
    ulonglong2 xa[4], xb[4];
    {
        const ulonglong2* x0 = xp + (size_t)t0 * 256;
#pragma unroll
        for (int q = 0; q < 4; q++) xa[q] = x0[q];
    }

    int t = t0;
    // ---- burn-in (no stores); nburn is 0 or 64, even. t+2 <= 288 < NT. ----
    for (int i = 0; i < nburn; i += 2) {
        const ulonglong2* x1 = xp + (size_t)(t + 1) * 256;
#pragma unroll
        for (int q = 0; q < 4; q++) xb[q] = x1[q];
        GRU_STEP(xa);
        const ulonglong2* x2 = xp + (size_t)(t + 2) * 256;
#pragma unroll
        for (int q = 0; q < 4; q++) xa[q] = x2[q];
        GRU_STEP(xb);
        t += 2;
    }

    // ---- stored steps (nstore even). Clamp the 2-ahead prefetch at T-1. ----
    for (int i = 0; i < nstore; i += 2) {
        const ulonglong2* x1 = xp + (size_t)(t + 1) * 256;   // t+1 <= NT-1 always
#pragma unroll
        for (int q = 0; q < 4; q++) xb[q] = x1[q];
        GRU_STEP(xa);
        op[(size_t)i * (NG * NH)] = h;

        const int t2 = (t + 2 < NT) ? (t + 2) : (NT - 1);
        const ulonglong2* x2 = xp + (size_t)t2 * 256;
#pragma unroll
        for (int q = 0; q < 4; q++) xa[q] = x2[q];
        GRU_STEP(xb);
        op[(size_t)(i + 1) * (NG * NH)] = h;
        t += 2;
    }
}

extern "C" void kernel_launch(void* const* d_in, const int* in_sizes, int n_in,
                              void* d_out, int out_size) {
    const float* x    = (const float*)d_in[0];
    const float* W_ih = (const float*)d_in[1];
    const float* W_hh = (const float*)d_in[2];
    const float* b_ih = (const float*)d_in[3];
    const float* b_hh = (const float*)d_in[4];
    float* out = (float*)d_out;

    // 4096 chains x 2 time-segments / 4 chains per warp / 4 warps per block
    mcgru_kernel<<<512, 128>>>(x, W_ih, W_hh, b_ih, b_hh, out);
}

// round 6
// speedup vs baseline: 1.7467x; 1.3425x over previous
#include <cuda_runtime.h>

// Problem constants
#define NG   64    // groups
#define ND   16    // per-group input dim
#define NH   8     // hidden per group
#define NB   64    // batch
#define NT   512   // timesteps

// T-split: 2 segments, balanced at 288 iterations each.
#define SEG0_STORE 288
#define BURN       64

// cp.async ring: 8 stages, prefetch distance 7
#define DEPTH 8
#define PDIST 7

typedef unsigned long long u64;

// ---------- packed f32x2 helpers ----------
__device__ __forceinline__ u64 pack2f(float lo, float hi) {
    u64 r;
    asm("mov.b64 %0, {%1,%2};" : "=l"(r) : "f"(lo), "f"(hi));
    return r;
}
__device__ __forceinline__ u64 fma2(u64 a, u64 b, u64 c) {
    u64 d;
    asm("fma.rn.f32x2 %0, %1, %2, %3;" : "=l"(d) : "l"(a), "l"(b), "l"(c));
    return d;
}
__device__ __forceinline__ float hsum2(u64 v) {
    float lo, hi;
    asm("mov.b64 {%0,%1}, %2;" : "=f"(lo), "=f"(hi) : "l"(v));
    return lo + hi;
}

// ---------- MUFU.TANH activations ----------
__device__ __forceinline__ float mufu_tanh(float v) {
    float r;
    asm("tanh.approx.f32 %0, %1;" : "=f"(r) : "f"(v));
    return r;
}
__device__ __forceinline__ float fast_sigmoid(float v) {
    return fmaf(0.5f, mufu_tanh(0.5f * v), 0.5f);
}

// ---------- cp.async ----------
__device__ __forceinline__ void cp_async16(unsigned smem_addr, const void* gptr) {
    asm volatile("cp.async.cg.shared.global [%0], [%1], 16;"
                 :: "r"(smem_addr), "l"(gptr));
}
__device__ __forceinline__ void cp_commit() {
    asm volatile("cp.async.commit_group;");
}
__device__ __forceinline__ void cp_wait6() {
    asm volatile("cp.async.wait_group 6;" ::: "memory");
}

// 128 threads/block (4 warps); each warp: 4 (b,g) chains of one time segment.
__global__ void __launch_bounds__(128, 4) mcgru_kernel(
    const float* __restrict__ x,      // [B, T, G*D]
    const float* __restrict__ W_ih,   // [G, 3H, D]
    const float* __restrict__ W_hh,   // [G, 3H, H]
    const float* __restrict__ b_ih,   // [G, 3H]
    const float* __restrict__ b_hh,   // [G, 3H]
    float* __restrict__ out)          // [B, T, G, H]
{
    // ring[warp][stage][chain][8 u64] = 4*8*4*64B = 8KB
    __shared__ __align__(16) u64 ring[4 * DEPTH * 4 * 8];

    const int w    = threadIdx.x >> 5;              // warp in block 0..3
    const int warp = blockIdx.x * 4 + w;            // 0..2047
    const int lane = threadIdx.x & 31;
    const int sub  = lane >> 3;                     // chain within warp 0..3
    const int l    = lane & 7;                      // hidden unit 0..7
    const int seg  = warp >> 10;                    // 0 or 1
    const int cbase = (warp & 1023) << 2;           // first chain id of this warp
    const int p    = cbase | sub;
    const int b    = p >> 6;
    const int g    = p & 63;

    // ---- per-lane weights (gate order: r rows 0..7, z 8..15, n 16..23) ----
    u64 wih2[3][8];     // input weights, packed pairs over d
    u64 whh2[3][4];     // hidden weights, packed pairs over j
#pragma unroll
    for (int r = 0; r < 3; r++) {
        const float* wr = W_ih + ((size_t)g * 24 + r * 8 + l) * ND;
#pragma unroll
        for (int q = 0; q < 8; q++) wih2[r][q] = pack2f(wr[2 * q], wr[2 * q + 1]);
        const float* wh = W_hh + ((size_t)g * 24 + r * 8 + l) * NH;
#pragma unroll
        for (int q = 0; q < 4; q++) whh2[r][q] = pack2f(wh[2 * q], wh[2 * q + 1]);
    }
    const u64 br2  = pack2f(b_ih[g * 24 + l]     + b_hh[g * 24 + l],     0.0f);
    const u64 bz2  = pack2f(b_ih[g * 24 + 8 + l] + b_hh[g * 24 + 8 + l], 0.0f);
    const u64 bxn2 = pack2f(b_ih[g * 24 + 16 + l], 0.0f);
    const u64 bhn2 = pack2f(b_hh[g * 24 + 16 + l], 0.0f);

    // ---- segment bounds ----
    const int t0     = seg ? (SEG0_STORE - BURN) : 0;           // 224 or 0
    const int nburn  = seg ? BURN : 0;                          // 64 or 0
    const int nsteps = seg ? (BURN + NT - SEG0_STORE) : SEG0_STORE;  // 288 both
    const int tlast  = t0 + nsteps - 1;

    // ---- producer setup (lanes 0..15): chain = lane>>2, 16B chunk = lane&3 ----
    const int pl  = cbase | (lane >> 2);
    const float* gsrc = x + (size_t)(pl >> 6) * NT * (NG * ND)
                          + (pl & 63) * ND + (lane & 3) * 4;
    const unsigned ring_w = (unsigned)__cvta_generic_to_shared(ring) + w * 2048;
    const unsigned prod_dst = ring_w + (lane & 15) * 16;   // + stage*256

    // consumer smem offset (bytes within warp's ring region): + stage*256
    const u64* cons_base = ring + (size_t)w * 256 + sub * 8;

    // output pointer: bumped every iteration; stores only when i >= nburn
    float* op = out + ((size_t)b * NT * NG + g) * NH + l
                    + ((size_t)t0) * (NG * NH);

    // ---- prologue: stages 0..6 <- t0..t0+6 ----
    if (lane < 16) {
#pragma unroll
        for (int s = 0; s < PDIST; s++) {
            cp_async16(prod_dst + s * 256, gsrc + (size_t)(t0 + s) * (NG * ND));
            cp_commit();
        }
    }

    float h = 0.0f;

#pragma unroll 2
    for (int i = 0; i < nsteps; i++) {
        // issue load for t0+i+7 into stage (i+7)&7 (clamped: re-reads tlast)
        const int tl = (t0 + i + PDIST <= tlast) ? (t0 + i + PDIST) : tlast;
        if (lane < 16) {
            cp_async16(prod_dst + (((unsigned)(i + PDIST) & 7) << 8),
                       gsrc + (size_t)tl * (NG * ND));
            cp_commit();
        }
        cp_wait6();
        __syncwarp();

        // consume stage i&7: 16 floats = 4 x 16B (broadcast across the 8 lanes)
        const ulonglong2* sp = reinterpret_cast<const ulonglong2*>(
            cons_base + (((unsigned)i & 7) << 5));
        ulonglong2 xq0 = sp[0], xq1 = sp[1], xq2 = sp[2], xq3 = sp[3];

        // gx accumulation (packed): r and z accumulators continue into gh
        u64 ar = br2, az = bz2, axn = bxn2;
        ar = fma2(wih2[0][0], xq0.x, ar); ar = fma2(wih2[0][1], xq0.y, ar);
        az = fma2(wih2[1][0], xq0.x, az); az = fma2(wih2[1][1], xq0.y, az);
        axn = fma2(wih2[2][0], xq0.x, axn); axn = fma2(wih2[2][1], xq0.y, axn);
        ar = fma2(wih2[0][2], xq1.x, ar); ar = fma2(wih2[0][3], xq1.y, ar);
        az = fma2(wih2[1][2], xq1.x, az); az = fma2(wih2[1][3], xq1.y, az);
        axn = fma2(wih2[2][2], xq1.x, axn); axn = fma2(wih2[2][3], xq1.y, axn);
        ar = fma2(wih2[0][4], xq2.x, ar); ar = fma2(wih2[0][5], xq2.y, ar);
        az = fma2(wih2[1][4], xq2.x, az); az = fma2(wih2[1][5], xq2.y, az);
        axn = fma2(wih2[2][4], xq2.x, axn); axn = fma2(wih2[2][5], xq2.y, axn);
        ar = fma2(wih2[0][6], xq3.x, ar); ar = fma2(wih2[0][7], xq3.y, ar);
        az = fma2(wih2[1][6], xq3.x, az); az = fma2(wih2[1][7], xq3.y, az);
        axn = fma2(wih2[2][6], xq3.x, axn); axn = fma2(wih2[2][7], xq3.y, axn);

        // hidden contribution: broadcast h, pack pairs, accumulate into ar/az
        const float h0 = __shfl_sync(0xffffffffu, h, 0, 8);
        const float h1 = __shfl_sync(0xffffffffu, h, 1, 8);
        const float h2 = __shfl_sync(0xffffffffu, h, 2, 8);
        const float h3 = __shfl_sync(0xffffffffu, h, 3, 8);
        const float h4 = __shfl_sync(0xffffffffu, h, 4, 8);
        const float h5 = __shfl_sync(0xffffffffu, h, 5, 8);
        const float h6 = __shfl_sync(0xffffffffu, h, 6, 8);
        const float h7 = __shfl_sync(0xffffffffu, h, 7, 8);
        u64 hp0 = pack2f(h0, h1), hp1 = pack2f(h2, h3);
        u64 hp2 = pack2f(h4, h5), hp3 = pack2f(h6, h7);

        u64 ahn = bhn2;
        ar = fma2(whh2[0][0], hp0, ar); az = fma2(whh2[1][0], hp0, az);
        ahn = fma2(whh2[2][0], hp0, ahn);
        ar = fma2(whh2[0][1], hp1, ar); az = fma2(whh2[1][1], hp1, az);
        ahn = fma2(whh2[2][1], hp1, ahn);
        ar = fma2(whh2[0][2], hp2, ar); az = fma2(whh2[1][2], hp2, az);
        ahn = fma2(whh2[2][2], hp2, ahn);
        ar = fma2(whh2[0][3], hp3, ar); az = fma2(whh2[1][3], hp3, az);
        ahn = fma2(whh2[2][3], hp3, ahn);

        const float rr  = fast_sigmoid(hsum2(ar));
        const float zz  = fast_sigmoid(hsum2(az));
        const float nn  = mufu_tanh(fmaf(rr, hsum2(ahn), hsum2(axn)));
        h = fmaf(zz, h - nn, nn);

        if (i >= nburn) *op = h;
        op += NG * NH;
    }
}

extern "C" void kernel_launch(void* const* d_in, const int* in_sizes, int n_in,
                              void* d_out, int out_size) {
    const float* x    = (const float*)d_in[0];
    const float* W_ih = (const float*)d_in[1];
    const float* W_hh = (const float*)d_in[2];
    const float* b_ih = (const float*)d_in[3];
    const float* b_hh = (const float*)d_in[4];
    float* out = (float*)d_out;

    // 4096 chains x 2 time-segments / 4 chains per warp / 4 warps per block
    mcgru_kernel<<<512, 128>>>(x, W_ih, W_hh, b_ih, b_hh, out);
}

// round 7
// speedup vs baseline: 1.9956x; 1.1425x over previous
#include <cuda_runtime.h>

// Problem constants
#define NG   64    // groups
#define ND   16    // per-group input dim
#define NH   8     // hidden per group
#define NB   64    // batch
#define NT   512   // timesteps

// T-split: 2 segments, balanced at 288 iterations each.
#define SEG0_STORE 288
#define BURN       64

// cp.async ring: 16 stages; 2 steps per commit group; wait_group 6 =>
// consumed stage was issued >= 12 steps earlier.
#define DEPTH 16

typedef unsigned long long u64;

// ---------- packed f32x2 helpers ----------
__device__ __forceinline__ u64 pack2f(float lo, float hi) {
    u64 r;
    asm("mov.b64 %0, {%1,%2};" : "=l"(r) : "f"(lo), "f"(hi));
    return r;
}
__device__ __forceinline__ u64 fma2(u64 a, u64 b, u64 c) {
    u64 d;
    asm("fma.rn.f32x2 %0, %1, %2, %3;" : "=l"(d) : "l"(a), "l"(b), "l"(c));
    return d;
}
__device__ __forceinline__ float hsum2(u64 v) {
    float lo, hi;
    asm("mov.b64 {%0,%1}, %2;" : "=f"(lo), "=f"(hi) : "l"(v));
    return lo + hi;
}

// ---------- MUFU.TANH activations ----------
__device__ __forceinline__ float mufu_tanh(float v) {
    float r;
    asm("tanh.approx.f32 %0, %1;" : "=f"(r) : "f"(v));
    return r;
}
__device__ __forceinline__ float fast_sigmoid(float v) {
    return fmaf(0.5f, mufu_tanh(0.5f * v), 0.5f);
}

// ---------- cp.async ----------
__device__ __forceinline__ void cp_async16(unsigned smem_addr, const void* gptr) {
    asm volatile("cp.async.cg.shared.global [%0], [%1], 16;"
                 :: "r"(smem_addr), "l"(gptr));
}
__device__ __forceinline__ void cp_commit() {
    asm volatile("cp.async.commit_group;");
}
__device__ __forceinline__ void cp_wait6() {
    asm volatile("cp.async.wait_group 6;" ::: "memory");
}

// One GRU step consuming 4 x ulonglong2 from smem pointer SP, updates h.
#define GRU_STEP(SP, OUT_PRED)                                                \
    do {                                                                      \
        ulonglong2 xq0 = (SP)[0], xq1 = (SP)[1], xq2 = (SP)[2], xq3 = (SP)[3];\
        u64 ar = br2, az = bz2, axn = bxn2;                                   \
        ar = fma2(wih2[0][0], xq0.x, ar); ar = fma2(wih2[0][1], xq0.y, ar);   \
        az = fma2(wih2[1][0], xq0.x, az); az = fma2(wih2[1][1], xq0.y, az);   \
        axn = fma2(wih2[2][0], xq0.x, axn); axn = fma2(wih2[2][1], xq0.y, axn);\
        ar = fma2(wih2[0][2], xq1.x, ar); ar = fma2(wih2[0][3], xq1.y, ar);   \
        az = fma2(wih2[1][2], xq1.x, az); az = fma2(wih2[1][3], xq1.y, az);   \
        axn = fma2(wih2[2][2], xq1.x, axn); axn = fma2(wih2[2][3], xq1.y, axn);\
        ar = fma2(wih2[0][4], xq2.x, ar); ar = fma2(wih2[0][5], xq2.y, ar);   \
        az = fma2(wih2[1][4], xq2.x, az); az = fma2(wih2[1][5], xq2.y, az);   \
        axn = fma2(wih2[2][4], xq2.x, axn); axn = fma2(wih2[2][5], xq2.y, axn);\
        ar = fma2(wih2[0][6], xq3.x, ar); ar = fma2(wih2[0][7], xq3.y, ar);   \
        az = fma2(wih2[1][6], xq3.x, az); az = fma2(wih2[1][7], xq3.y, az);   \
        axn = fma2(wih2[2][6], xq3.x, axn); axn = fma2(wih2[2][7], xq3.y, axn);\
        const float h0 = __shfl_sync(0xffffffffu, h, 0, 8);                   \
        const float h1 = __shfl_sync(0xffffffffu, h, 1, 8);                   \
        const float h2 = __shfl_sync(0xffffffffu, h, 2, 8);                   \
        const float h3 = __shfl_sync(0xffffffffu, h, 3, 8);                   \
        const float h4 = __shfl_sync(0xffffffffu, h, 4, 8);                   \
        const float h5 = __shfl_sync(0xffffffffu, h, 5, 8);                   \
        const float h6 = __shfl_sync(0xffffffffu, h, 6, 8);                   \
        const float h7 = __shfl_sync(0xffffffffu, h, 7, 8);                   \
        u64 hp0 = pack2f(h0, h1), hp1 = pack2f(h2, h3);                       \
        u64 hp2 = pack2f(h4, h5), hp3 = pack2f(h6, h7);                       \
        u64 ahn = bhn2;                                                       \
        ar = fma2(whh2[0][0], hp0, ar); az = fma2(whh2[1][0], hp0, az);       \
        ahn = fma2(whh2[2][0], hp0, ahn);                                     \
        ar = fma2(whh2[0][1], hp1, ar); az = fma2(whh2[1][1], hp1, az);       \
        ahn = fma2(whh2[2][1], hp1, ahn);                                     \
        ar = fma2(whh2[0][2], hp2, ar); az = fma2(whh2[1][2], hp2, az);       \
        ahn = fma2(whh2[2][2], hp2, ahn);                                     \
        ar = fma2(whh2[0][3], hp3, ar); az = fma2(whh2[1][3], hp3, az);       \
        ahn = fma2(whh2[2][3], hp3, ahn);                                     \
        const float rr  = fast_sigmoid(hsum2(ar));                            \
        const float zz  = fast_sigmoid(hsum2(az));                           \
        const float nn  = mufu_tanh(fmaf(rr, hsum2(ahn), hsum2(axn)));        \
        h = fmaf(zz, h - nn, nn);                                             \
        if (OUT_PRED) *op = h;                                                \
        op += NG * NH;                                                        \
    } while (0)

// 128 threads/block (4 warps); each warp: 4 (b,g) chains of one time segment.
__global__ void __launch_bounds__(128, 4) mcgru_kernel(
    const float* __restrict__ x,      // [B, T, G*D]
    const float* __restrict__ W_ih,   // [G, 3H, D]
    const float* __restrict__ W_hh,   // [G, 3H, H]
    const float* __restrict__ b_ih,   // [G, 3H]
    const float* __restrict__ b_hh,   // [G, 3H]
    float* __restrict__ out)          // [B, T, G, H]
{
    // ring[warp][stage][chain][8 u64] = 4 * 16 * 4 * 64B = 16KB
    __shared__ __align__(16) u64 ring[4 * DEPTH * 4 * 8];

    const int w    = threadIdx.x >> 5;              // warp in block 0..3
    const int warp = blockIdx.x * 4 + w;            // 0..2047
    const int lane = threadIdx.x & 31;
    const int sub  = lane >> 3;                     // chain within warp 0..3
    const int l    = lane & 7;                      // hidden unit 0..7
    const int seg  = warp >> 10;                    // 0 or 1
    const int cbase = (warp & 1023) << 2;           // first chain id of this warp
    const int p    = cbase | sub;
    const int b    = p >> 6;
    const int g    = p & 63;

    // ---- per-lane weights (gate order: r rows 0..7, z 8..15, n 16..23) ----
    u64 wih2[3][8];     // input weights, packed pairs over d
    u64 whh2[3][4];     // hidden weights, packed pairs over j
#pragma unroll
    for (int r = 0; r < 3; r++) {
        const float* wr = W_ih + ((size_t)g * 24 + r * 8 + l) * ND;
#pragma unroll
        for (int q = 0; q < 8; q++) wih2[r][q] = pack2f(wr[2 * q], wr[2 * q + 1]);
        const float* wh = W_hh + ((size_t)g * 24 + r * 8 + l) * NH;
#pragma unroll
        for (int q = 0; q < 4; q++) whh2[r][q] = pack2f(wh[2 * q], wh[2 * q + 1]);
    }
    const u64 br2  = pack2f(b_ih[g * 24 + l]     + b_hh[g * 24 + l],     0.0f);
    const u64 bz2  = pack2f(b_ih[g * 24 + 8 + l] + b_hh[g * 24 + 8 + l], 0.0f);
    const u64 bxn2 = pack2f(b_ih[g * 24 + 16 + l], 0.0f);
    const u64 bhn2 = pack2f(b_hh[g * 24 + 16 + l], 0.0f);

    // ---- segment bounds ----
    const int t0     = seg ? (SEG0_STORE - BURN) : 0;                // 224 or 0
    const int nburn  = seg ? BURN : 0;                               // 64 or 0
    const int nsteps = seg ? (BURN + NT - SEG0_STORE) : SEG0_STORE;  // 288 both
    const int tlast  = t0 + nsteps - 1;

    // ---- producer: all 32 lanes, 2 timesteps per round ----
    // lane&15 -> (chain = (lane&15)>>2, 16B chunk = lane&3); lane>>4 -> +0/+1 step
    const int pl  = cbase | ((lane & 15) >> 2);
    const int dt  = lane >> 4;                      // 0 or 1
    const float* gsrc = x + (size_t)(pl >> 6) * NT * (NG * ND)
                          + (pl & 63) * ND + (lane & 3) * 4;
    const unsigned ring_w = (unsigned)__cvta_generic_to_shared(ring) + w * (DEPTH * 256);
    const unsigned prod_dst = ring_w + (lane & 15) * 16;   // + stage*256

    // consumer base (u64 units within ring): warp region + chain offset
    const u64* cons_base = ring + (size_t)w * (DEPTH * 32) + sub * 8;

    // output pointer: bumped every step; stores only when i >= nburn
    float* op = out + ((size_t)b * NT * NG + g) * NH + l
                    + ((size_t)t0) * (NG * NH);

    // ---- prologue: stages 0..13 <- steps t0..t0+13 (7 commit groups) ----
#pragma unroll
    for (int s = 0; s < 7; s++) {
        cp_async16(prod_dst + ((2 * s + dt) << 8),
                   gsrc + (size_t)(t0 + 2 * s + dt) * (NG * ND));
        cp_commit();
    }

    float h = 0.0f;

#pragma unroll 2
    for (int i = 0; i < nsteps; i += 2) {
        // issue loads for steps i+14, i+15 into stages (i+14..15)&15 (clamped)
        {
            const int ts = t0 + i + 14 + dt;
            const int tl = (ts <= tlast) ? ts : tlast;
            cp_async16(prod_dst + ((((unsigned)(i + 14) & 15) + dt) << 8),
                       gsrc + (size_t)tl * (NG * ND));
            cp_commit();
        }
        // 6 newest groups may be in flight => steps <= i+3 complete; stages i, i+1 ready
        cp_wait6();
        __syncwarp();

        const u64* sp0 = cons_base + (((unsigned)i & 15) << 5);
        GRU_STEP(reinterpret_cast<const ulonglong2*>(sp0), (i >= nburn));
        const u64* sp1 = cons_base + ((((unsigned)i + 1) & 15) << 5);
        GRU_STEP(reinterpret_cast<const ulonglong2*>(sp1), (i + 1 >= nburn));
    }
}

extern "C" void kernel_launch(void* const* d_in, const int* in_sizes, int n_in,
                              void* d_out, int out_size) {
    const float* x    = (const float*)d_in[0];
    const float* W_ih = (const float*)d_in[1];
    const float* W_hh = (const float*)d_in[2];
    const float* b_ih = (const float*)d_in[3];
    const float* b_hh = (const float*)d_in[4];
    float* out = (float*)d_out;

    // 4096 chains x 2 time-segments / 4 chains per warp / 4 warps per block
    mcgru_kernel<<<512, 128>>>(x, W_ih, W_hh, b_ih, b_hh, out);
}